// round 2
// baseline (speedup 1.0000x reference)
#include <cuda_runtime.h>
#include <cstdint>

#define B_ 2
#define D_ 96
#define H_ 96
#define W_ 96
#define L_ (H_*W_)        // 9216
#define K_ 4
#define N_ 16
#define R_ 6
#define CDIM (R_ + 2*N_)  // 38

// Scratch (allocation-free: __device__ globals)
__device__ float g_dd[B_*K_*L_*D_*2];   // (bk, l, d, {delta, delta*u})  ~56.6MB
__device__ float g_bc[B_*K_*L_*N_*2];   // (bk, l, n, {B, C})            ~9.4MB
__device__ float g_y [B_*K_*L_*D_];     // (bk, l, d)                    ~28.3MB
__device__ float g_Ahat[K_*D_*N_];      // -exp(A_logs)*log2(e)

__device__ __forceinline__ float ex2f(float x){
    float y; asm("ex2.approx.ftz.f32 %0, %1;" : "=f"(y) : "f"(x)); return y;
}
__device__ __forceinline__ void cp16(void* dst_smem, const void* src){
    unsigned s = (unsigned)__cvta_generic_to_shared(dst_smem);
    asm volatile("cp.async.ca.shared.global [%0], [%1], 16;\n" :: "r"(s), "l"(src));
}
__device__ __forceinline__ void cp_commit(){ asm volatile("cp.async.commit_group;\n"); }
template<int n> __device__ __forceinline__ void cp_wait(){
    asm volatile("cp.async.wait_group %0;\n" :: "n"(n));
}

// ---------------------------------------------------------------------------
// Kernel 0: Ahat = -exp(A_logs) * log2(e)
// ---------------------------------------------------------------------------
__global__ void ahat_kernel(const float* __restrict__ A_logs){
    int i = blockIdx.x*256 + threadIdx.x;
    if (i < K_*D_*N_) g_Ahat[i] = -expf(A_logs[i]) * 1.4426950408889634f;
}

// ---------------------------------------------------------------------------
// Kernel 1: projection. Per (b,k, 32-l tile): gather xs, x_dbl = W @ xs,
// dts = dtw @ x_dbl[:R], delta = softplus(dts+bias), emit (delta, delta*u),
// (B, C) in scan-friendly interleaved layouts.
// ---------------------------------------------------------------------------
__global__ __launch_bounds__(128) void proj_kernel(
    const float* __restrict__ x, const float* __restrict__ xpw,
    const float* __restrict__ dtw, const float* __restrict__ dtb)
{
    __shared__ float xt[D_*33];        // xs tile [d][l], padded
    __shared__ float ws[CDIM*97];      // proj weights, padded
    __shared__ float cbuf[CDIM*33];    // x_dbl tile [c][l]

    int bk = blockIdx.x; int b = bk>>2; int k = bk&3;
    int l0 = blockIdx.y*32;
    int tid = threadIdx.x;

    for (int i = tid; i < CDIM*D_; i += 128){
        int c = i/D_, d = i - c*D_;
        ws[c*97+d] = xpw[k*CDIM*D_ + i];
    }
    const float* xb = x + (size_t)b*D_*L_;
    for (int i = tid; i < D_*32; i += 128){
        int d = i>>5, l = i&31;
        int ll = l0 + l;
        int pos;
        if (k==0) pos = ll;
        else if (k==2) pos = L_-1-ll;
        else {
            int lv = (k==1) ? ll : (L_-1-ll);
            int w = lv / H_, h = lv - w*H_;
            pos = h*W_ + w;
        }
        xt[d*33 + l] = xb[(size_t)d*L_ + pos];
    }
    __syncthreads();

    // register-tiled 38x32 = (c) x (l) GEMM over d=96
    int ci = tid & 15, lj = tid >> 4;
    float a0[4]={0,0,0,0}, a1[4]={0,0,0,0}, a2[4]={0,0,0,0};
    #pragma unroll 4
    for (int d = 0; d < D_; d++){
        float w0 = ws[ci*97+d];
        float w1 = ws[(ci+16)*97+d];
        float w2 = (ci<6) ? ws[(ci+32)*97+d] : 0.f;
        #pragma unroll
        for (int j=0;j<4;j++){
            float xv = xt[d*33 + lj*4 + j];
            a0[j] = fmaf(w0, xv, a0[j]);
            a1[j] = fmaf(w1, xv, a1[j]);
            a2[j] = fmaf(w2, xv, a2[j]);
        }
    }
    #pragma unroll
    for (int j=0;j<4;j++){
        int l = lj*4+j;
        cbuf[ci*33 + l] = a0[j];
        cbuf[(ci+16)*33 + l] = a1[j];
        if (ci<6) cbuf[(ci+32)*33 + l] = a2[j];
    }
    __syncthreads();

    if (tid < D_){
        int d = tid;
        float wr[R_];
        #pragma unroll
        for (int r=0;r<R_;r++) wr[r] = dtw[(k*D_+d)*R_ + r];
        float bias = dtb[k*D_+d];
        for (int l=0;l<32;l++){
            float s = bias;
            #pragma unroll
            for (int r=0;r<R_;r++) s = fmaf(cbuf[r*33+l], wr[r], s);
            float dlt = (s > 20.f) ? s : log1pf(__expf(s));
            float u = xt[d*33+l];
            float2 v; v.x = dlt; v.y = dlt*u;
            *(float2*)&g_dd[(((size_t)bk*L_ + (l0+l))*D_ + d)*2] = v;
        }
    } else if (tid < D_ + N_){
        int n = tid - D_;
        for (int l=0;l<32;l++){
            float2 v;
            v.x = cbuf[(R_+n)*33 + l];
            v.y = cbuf[(R_+N_+n)*33 + l];
            *(float2*)&g_bc[(((size_t)bk*L_ + (l0+l))*N_ + n)*2] = v;
        }
    }
}

// ---------------------------------------------------------------------------
// Kernel 2: selective scan. 96 blocks x 128 thr; block = (bk, 8 d-chains).
// Warp = 2 chains, lane = state index n. cp.async double-buffered staging.
// ---------------------------------------------------------------------------
#define CH 96
__global__ __launch_bounds__(128) void scan_kernel()
{
    __shared__ __align__(16) float s_dd[2][CH*16];  // [l][8 chains][2]
    __shared__ __align__(16) float s_bc[2][CH*32];  // [l][16 n][2]
    __shared__ __align__(16) float s_y [CH*8];

    int bk = blockIdx.x / 12; int dblk = blockIdx.x % 12; int d0 = dblk*8;
    int k = bk & 3;
    int tid = threadIdx.x;
    int wid = tid>>5, lane = tid&31;
    int g = lane>>4, n = lane&15;
    int cidx = wid*2+g;
    int d = d0 + cidx;
    float Ah = g_Ahat[(k*D_+d)*N_ + n];
    float h = 0.f;

    const float* gdd = g_dd + (size_t)bk*L_*D_*2;
    const float* gbc = g_bc + (size_t)bk*L_*N_*2;
    float* gy = g_y + (size_t)bk*L_*D_;

    // prefetch chunk 0
    {
        for (int i = tid; i < CH*4; i += 128){
            int l = i>>2, q = i&3;
            cp16(&s_dd[0][l*16 + q*4], gdd + ((size_t)l*D_ + d0)*2 + q*4);
        }
        for (int i = tid; i < CH*8; i += 128){
            int l = i>>3, q = i&7;
            cp16(&s_bc[0][l*32 + q*4], gbc + (size_t)l*N_*2 + q*4);
        }
        cp_commit();
    }

    const int NCH = L_/CH;
    for (int c = 0; c < NCH; c++){
        int buf = c & 1;
        if (c+1 < NCH){
            int lb = (c+1)*CH;
            for (int i = tid; i < CH*4; i += 128){
                int l = i>>2, q = i&3;
                cp16(&s_dd[buf^1][l*16 + q*4], gdd + ((size_t)(lb+l)*D_ + d0)*2 + q*4);
            }
            for (int i = tid; i < CH*8; i += 128){
                int l = i>>3, q = i&7;
                cp16(&s_bc[buf^1][l*32 + q*4], gbc + (size_t)(lb+l)*N_*2 + q*4);
            }
            cp_commit();
            cp_wait<1>();
        } else {
            cp_wait<0>();
        }
        __syncthreads();

        #pragma unroll 4
        for (int t = 0; t < CH; t++){
            float2 dd = *(const float2*)&s_dd[buf][t*16 + cidx*2];
            float2 bc = *(const float2*)&s_bc[buf][t*32 + n*2];
            float a = ex2f(dd.x * Ah);           // exp(delta * A)
            h = fmaf(a, h, dd.y * bc.x);         // h = a*h + (delta*u)*B
            float p = h * bc.y;                  // h*C
            p += __shfl_xor_sync(0xffffffffu, p, 8);
            p += __shfl_xor_sync(0xffffffffu, p, 4);
            p += __shfl_xor_sync(0xffffffffu, p, 2);
            p += __shfl_xor_sync(0xffffffffu, p, 1);
            if (n == 0) s_y[t*8 + cidx] = p;
        }
        __syncthreads();

        int lbase = c*CH;
        for (int i = tid; i < CH*2; i += 128){
            int l = i>>1, half = i&1;
            *(float4*)&gy[(size_t)(lbase+l)*D_ + d0 + half*4] =
                *(float4*)&s_y[l*8 + half*4];
        }
    }
}

// ---------------------------------------------------------------------------
// Kernel 3: cross-merge + Ds*x + LayerNorm(D). Warp per pixel.
// ---------------------------------------------------------------------------
__global__ __launch_bounds__(128) void merge_kernel(
    const float* __restrict__ x, const float* __restrict__ Ds,
    const float* __restrict__ nw, const float* __restrict__ nb,
    float* __restrict__ out)
{
    int wid = threadIdx.x>>5, lane = threadIdx.x&31;
    int pix = blockIdx.x*4 + wid;
    int b = pix / L_;
    int rem = pix - b*L_;
    int hh = rem / W_;
    int ww = rem - hh*W_;
    int l_wh = ww*H_ + hh;

    const float* y0 = g_y + ((size_t)(b*4+0)*L_ + rem)*D_;
    const float* y1 = g_y + ((size_t)(b*4+1)*L_ + l_wh)*D_;
    const float* y2 = g_y + ((size_t)(b*4+2)*L_ + (L_-1-rem))*D_;
    const float* y3 = g_y + ((size_t)(b*4+3)*L_ + (L_-1-l_wh))*D_;

    float v[3]; float s = 0.f, ss = 0.f;
    #pragma unroll
    for (int j=0;j<3;j++){
        int d = lane + 32*j;
        float dsum = Ds[d] + Ds[D_+d] + Ds[2*D_+d] + Ds[3*D_+d];
        float acc = y0[d] + y1[d] + y2[d] + y3[d]
                  + x[((size_t)b*D_ + d)*L_ + rem] * dsum;
        v[j] = acc; s += acc; ss = fmaf(acc, acc, ss);
    }
    #pragma unroll
    for (int o=16;o>0;o>>=1){
        s  += __shfl_xor_sync(0xffffffffu, s,  o);
        ss += __shfl_xor_sync(0xffffffffu, ss, o);
    }
    float mu  = s * (1.f/D_);
    float var = ss * (1.f/D_) - mu*mu;
    float rstd = rsqrtf(var + 1e-5f);
    float* op = out + (size_t)pix*D_;
    #pragma unroll
    for (int j=0;j<3;j++){
        int d = lane + 32*j;
        op[d] = (v[j]-mu)*rstd*nw[d] + nb[d];
    }
}

// ---------------------------------------------------------------------------
extern "C" void kernel_launch(void* const* d_in, const int* in_sizes, int n_in,
                              void* d_out, int out_size)
{
    const float* x      = (const float*)d_in[0];
    const float* xpw    = (const float*)d_in[1];
    const float* dtw    = (const float*)d_in[2];
    const float* dtb    = (const float*)d_in[3];
    const float* A_logs = (const float*)d_in[4];
    const float* Ds     = (const float*)d_in[5];
    const float* nw     = (const float*)d_in[6];
    const float* nb     = (const float*)d_in[7];
    float* out = (float*)d_out;

    ahat_kernel<<<(K_*D_*N_+255)/256, 256>>>(A_logs);
    proj_kernel<<<dim3(B_*K_, L_/32), 128>>>(x, xpw, dtw, dtb);
    scan_kernel<<<B_*K_*12, 128>>>();
    merge_kernel<<<(B_*L_)/4, 128>>>(x, Ds, nw, nb, out);
}

// round 4
// speedup vs baseline: 1.9857x; 1.9857x over previous
#include <cuda_runtime.h>
#include <cstdint>

#define B_ 2
#define D_ 96
#define H_ 96
#define W_ 96
#define L_ (H_*W_)        // 9216
#define K_ 4
#define N_ 16
#define R_ 6
#define CDIM (R_ + 2*N_)  // 38

// Scratch (allocation-free: __device__ globals)
__device__ float g_dd[B_*K_*L_*D_*2];   // (bk, l, d, {delta, delta*u})
__device__ float g_bc[B_*K_*L_*N_*2];   // (bk, l, n, {B, C})
__device__ float g_y [B_*K_*L_*D_];     // (bk, l, d)

__device__ __forceinline__ float ex2f(float x){
    float y; asm("ex2.approx.ftz.f32 %0, %1;" : "=f"(y) : "f"(x)); return y;
}
__device__ __forceinline__ void cp16(void* dst_smem, const void* src){
    unsigned s = (unsigned)__cvta_generic_to_shared(dst_smem);
    asm volatile("cp.async.ca.shared.global [%0], [%1], 16;\n" :: "r"(s), "l"(src));
}
__device__ __forceinline__ void cp_commit(){ asm volatile("cp.async.commit_group;\n"); }
template<int n> __device__ __forceinline__ void cp_wait(){
    asm volatile("cp.async.wait_group %0;\n" :: "n"(n));
}

// ---------------------------------------------------------------------------
// Kernel 1: projection (unchanged — known-correct)
// ---------------------------------------------------------------------------
__global__ __launch_bounds__(128) void proj_kernel(
    const float* __restrict__ x, const float* __restrict__ xpw,
    const float* __restrict__ dtw, const float* __restrict__ dtb)
{
    __shared__ float xt[D_*33];
    __shared__ float ws[CDIM*97];
    __shared__ float cbuf[CDIM*33];

    int bk = blockIdx.x; int b = bk>>2; int k = bk&3;
    int l0 = blockIdx.y*32;
    int tid = threadIdx.x;

    for (int i = tid; i < CDIM*D_; i += 128){
        int c = i/D_, d = i - c*D_;
        ws[c*97+d] = xpw[k*CDIM*D_ + i];
    }
    const float* xb = x + (size_t)b*D_*L_;
    for (int i = tid; i < D_*32; i += 128){
        int d = i>>5, l = i&31;
        int ll = l0 + l;
        int pos;
        if (k==0) pos = ll;
        else if (k==2) pos = L_-1-ll;
        else {
            int lv = (k==1) ? ll : (L_-1-ll);
            int w = lv / H_, h = lv - w*H_;
            pos = h*W_ + w;
        }
        xt[d*33 + l] = xb[(size_t)d*L_ + pos];
    }
    __syncthreads();

    int ci = tid & 15, lj = tid >> 4;
    float a0[4]={0,0,0,0}, a1[4]={0,0,0,0}, a2[4]={0,0,0,0};
    #pragma unroll 4
    for (int d = 0; d < D_; d++){
        float w0 = ws[ci*97+d];
        float w1 = ws[(ci+16)*97+d];
        float w2 = (ci<6) ? ws[(ci+32)*97+d] : 0.f;
        #pragma unroll
        for (int j=0;j<4;j++){
            float xv = xt[d*33 + lj*4 + j];
            a0[j] = fmaf(w0, xv, a0[j]);
            a1[j] = fmaf(w1, xv, a1[j]);
            a2[j] = fmaf(w2, xv, a2[j]);
        }
    }
    #pragma unroll
    for (int j=0;j<4;j++){
        int l = lj*4+j;
        cbuf[ci*33 + l] = a0[j];
        cbuf[(ci+16)*33 + l] = a1[j];
        if (ci<6) cbuf[(ci+32)*33 + l] = a2[j];
    }
    __syncthreads();

    if (tid < D_){
        int d = tid;
        float wr[R_];
        #pragma unroll
        for (int r=0;r<R_;r++) wr[r] = dtw[(k*D_+d)*R_ + r];
        float bias = dtb[k*D_+d];
        for (int l=0;l<32;l++){
            float s = bias;
            #pragma unroll
            for (int r=0;r<R_;r++) s = fmaf(cbuf[r*33+l], wr[r], s);
            float dlt = (s > 20.f) ? s : log1pf(__expf(s));
            float u = xt[d*33+l];
            float2 v; v.x = dlt; v.y = dlt*u;
            *(float2*)&g_dd[(((size_t)bk*L_ + (l0+l))*D_ + d)*2] = v;
        }
    } else if (tid < D_ + N_){
        int n = tid - D_;
        for (int l=0;l<32;l++){
            float2 v;
            v.x = cbuf[(R_+n)*33 + l];
            v.y = cbuf[(R_+N_+n)*33 + l];
            *(float2*)&g_bc[(((size_t)bk*L_ + (l0+l))*N_ + n)*2] = v;
        }
    }
}

// ---------------------------------------------------------------------------
// Kernel 2: selective scan. 96 blocks x 128 thr; block = (bk, 8 d-chains).
// Warp = 2 chains, lane = state n. Per-step: STS the h*C partial (no cross-
// lane reduction on the serial path); block-reduce partials once per chunk.
// ---------------------------------------------------------------------------
#define CH 48
#define PROW 132   // padded partial row (floats) to dodge 64B-stride conflicts
__global__ __launch_bounds__(128) void scan_kernel(const float* __restrict__ A_logs)
{
    __shared__ __align__(16) float s_dd[2][CH*16];  // [l][8 chains][2]
    __shared__ __align__(16) float s_bc[2][CH*32];  // [l][16 n][2]
    __shared__ __align__(16) float s_p [CH*PROW];   // per-step partials

    int bk = blockIdx.x / 12; int dblk = blockIdx.x % 12; int d0 = dblk*8;
    int k = bk & 3;
    int tid = threadIdx.x;
    int wid = tid>>5, lane = tid&31;
    int g = lane>>4, n = lane&15;
    int cidx = wid*2+g;
    int d = d0 + cidx;
    float Ah = -expf(A_logs[(k*D_+d)*N_ + n]) * 1.4426950408889634f;
    float h = 0.f;

    const float* gdd = g_dd + (size_t)bk*L_*D_*2;
    const float* gbc = g_bc + (size_t)bk*L_*N_*2;
    float* gy = g_y + (size_t)bk*L_*D_;

    // prefetch chunk 0
    {
        for (int i = tid; i < CH*4; i += 128){
            int l = i>>2, q = i&3;
            cp16(&s_dd[0][l*16 + q*4], gdd + ((size_t)l*D_ + d0)*2 + q*4);
        }
        for (int i = tid; i < CH*8; i += 128){
            int l = i>>3, q = i&7;
            cp16(&s_bc[0][l*32 + q*4], gbc + (size_t)l*N_*2 + q*4);
        }
        cp_commit();
    }

    const int NCH = L_/CH;
    for (int c = 0; c < NCH; c++){
        int buf = c & 1;
        if (c+1 < NCH){
            int lb = (c+1)*CH;
            for (int i = tid; i < CH*4; i += 128){
                int l = i>>2, q = i&3;
                cp16(&s_dd[buf^1][l*16 + q*4], gdd + ((size_t)(lb+l)*D_ + d0)*2 + q*4);
            }
            for (int i = tid; i < CH*8; i += 128){
                int l = i>>3, q = i&7;
                cp16(&s_bc[buf^1][l*32 + q*4], gbc + (size_t)(lb+l)*N_*2 + q*4);
            }
            cp_commit();
            cp_wait<1>();
        } else {
            cp_wait<0>();
        }
        __syncthreads();

        const float* pdd = &s_dd[buf][cidx*2];
        const float* pbc = &s_bc[buf][n*2];
        float* pp = &s_p[wid*32 + lane];
        #pragma unroll 8
        for (int t = 0; t < CH; t++){
            float2 dd = *(const float2*)(pdd + t*16);
            float2 bc = *(const float2*)(pbc + t*32);
            float a = ex2f(dd.x * Ah);           // exp(delta * A)
            h = fmaf(a, h, dd.y * bc.x);         // h = a*h + (delta*u)*B
            pp[t*PROW] = h * bc.y;               // partial; reduce later
        }
        __syncthreads();

        // reduce 16 partials per (l, chain) and store y
        int lbase = c*CH;
        for (int j = tid; j < CH*8; j += 128){
            int l = j>>3, c8 = j&7;
            const float4* q = (const float4*)&s_p[l*PROW + c8*16];
            float4 v0=q[0], v1=q[1], v2=q[2], v3=q[3];
            float s = ((v0.x+v0.y)+(v0.z+v0.w)) + ((v1.x+v1.y)+(v1.z+v1.w))
                    + ((v2.x+v2.y)+(v2.z+v2.w)) + ((v3.x+v3.y)+(v3.z+v3.w));
            gy[(size_t)(lbase+l)*D_ + d0 + c8] = s;
        }
        __syncthreads();   // protect s_p / s_dd[buf] before next chunk reuses
    }
}

// ---------------------------------------------------------------------------
// Kernel 3: cross-merge + Ds*x + LayerNorm(D). x staged via smem (coalesced).
// ---------------------------------------------------------------------------
__global__ __launch_bounds__(128) void merge_kernel(
    const float* __restrict__ x, const float* __restrict__ Ds,
    const float* __restrict__ nw, const float* __restrict__ nb,
    float* __restrict__ out)
{
    __shared__ float xt[D_*33];
    int tid = threadIdx.x;
    int pix0 = blockIdx.x*32;
    int b = pix0 / L_;
    int rem0 = pix0 - b*L_;

    const float* xb = x + (size_t)b*D_*L_;
    for (int i = tid; i < D_*32; i += 128){
        int dd = i>>5, p = i&31;
        xt[dd*33 + p] = xb[(size_t)dd*L_ + rem0 + p];
    }
    __syncthreads();

    int wid = tid>>5, lane = tid&31;
    for (int pp = wid; pp < 32; pp += 4){
        int rem = rem0 + pp;
        int hh = rem / W_;
        int ww = rem - hh*W_;
        int l_wh = ww*H_ + hh;

        const float* y0 = g_y + ((size_t)(b*4+0)*L_ + rem)*D_;
        const float* y1 = g_y + ((size_t)(b*4+1)*L_ + l_wh)*D_;
        const float* y2 = g_y + ((size_t)(b*4+2)*L_ + (L_-1-rem))*D_;
        const float* y3 = g_y + ((size_t)(b*4+3)*L_ + (L_-1-l_wh))*D_;

        float v[3]; float s = 0.f, ss = 0.f;
        #pragma unroll
        for (int j=0;j<3;j++){
            int dd = lane + 32*j;
            float dsum = Ds[dd] + Ds[D_+dd] + Ds[2*D_+dd] + Ds[3*D_+dd];
            float acc = y0[dd] + y1[dd] + y2[dd] + y3[dd] + xt[dd*33+pp] * dsum;
            v[j] = acc; s += acc; ss = fmaf(acc, acc, ss);
        }
        #pragma unroll
        for (int o=16;o>0;o>>=1){
            s  += __shfl_xor_sync(0xffffffffu, s,  o);
            ss += __shfl_xor_sync(0xffffffffu, ss, o);
        }
        float mu  = s * (1.f/D_);
        float var = ss * (1.f/D_) - mu*mu;
        float rstd = rsqrtf(var + 1e-5f);
        float* op = out + ((size_t)b*L_ + rem)*D_;
        #pragma unroll
        for (int j=0;j<3;j++){
            int dd = lane + 32*j;
            op[dd] = (v[j]-mu)*rstd*nw[dd] + nb[dd];
        }
    }
}

// ---------------------------------------------------------------------------
extern "C" void kernel_launch(void* const* d_in, const int* in_sizes, int n_in,
                              void* d_out, int out_size)
{
    const float* x      = (const float*)d_in[0];
    const float* xpw    = (const float*)d_in[1];
    const float* dtw    = (const float*)d_in[2];
    const float* dtb    = (const float*)d_in[3];
    const float* A_logs = (const float*)d_in[4];
    const float* Ds     = (const float*)d_in[5];
    const float* nw     = (const float*)d_in[6];
    const float* nb     = (const float*)d_in[7];
    float* out = (float*)d_out;

    proj_kernel<<<dim3(B_*K_, L_/32), 128>>>(x, xpw, dtw, dtb);
    scan_kernel<<<B_*K_*12, 128>>>(A_logs);
    merge_kernel<<<B_*L_/32, 128>>>(x, Ds, nw, nb, out);
}

// round 5
// speedup vs baseline: 3.2895x; 1.6566x over previous
#include <cuda_runtime.h>
#include <cstdint>

#define B_ 2
#define D_ 96
#define H_ 96
#define W_ 96
#define L_ (H_*W_)        // 9216
#define K_ 4
#define N_ 16
#define R_ 6
#define CDIM (R_ + 2*N_)  // 38

// Scratch (allocation-free: __device__ globals)
__device__ float g_dd[B_*K_*L_*D_*2];   // (bk, l, d, {delta, delta*u})
__device__ float g_bc[B_*K_*L_*N_*2];   // (bk, l, n, {B, C})
__device__ float g_y [B_*K_*L_*D_];     // (bk, l, d)

__device__ __forceinline__ float ex2f(float x){
    float y; asm("ex2.approx.ftz.f32 %0, %1;" : "=f"(y) : "f"(x)); return y;
}
__device__ __forceinline__ void cp16(void* dst_smem, const void* src){
    unsigned s = (unsigned)__cvta_generic_to_shared(dst_smem);
    asm volatile("cp.async.ca.shared.global [%0], [%1], 16;\n" :: "r"(s), "l"(src));
}
__device__ __forceinline__ void cp_commit(){ asm volatile("cp.async.commit_group;\n"); }
template<int n> __device__ __forceinline__ void cp_wait(){
    asm volatile("cp.async.wait_group %0;\n" :: "n"(n));
}

// ---------------------------------------------------------------------------
// Kernel 1: projection. Block = (b,k) x 128-l tile (4 subtiles of 32),
// weights loaded to smem once per block.
// ---------------------------------------------------------------------------
__global__ __launch_bounds__(128) void proj_kernel(
    const float* __restrict__ x, const float* __restrict__ xpw,
    const float* __restrict__ dtw, const float* __restrict__ dtb)
{
    __shared__ float xt[D_*36];        // xs tile [d][l], padded 36 (16B-aligned rows)
    __shared__ float ws[CDIM*97];      // proj weights
    __shared__ float wdT[R_*D_];       // dt weights transposed [r][d]
    __shared__ float sbias[D_];
    __shared__ float cbuf[CDIM*33];    // x_dbl tile [c][l]

    int bk = blockIdx.x; int b = bk>>2; int k = bk&3;
    int tid = threadIdx.x;

    for (int i = tid; i < CDIM*D_; i += 128){
        int c = i/D_, d = i - c*D_;
        ws[c*97+d] = xpw[k*CDIM*D_ + i];
    }
    for (int i = tid; i < D_*R_; i += 128){
        int d = i/R_, r = i - d*R_;
        wdT[r*D_+d] = dtw[k*D_*R_ + i];
    }
    if (tid < D_) sbias[tid] = dtb[k*D_+tid];

    const float* xb = x + (size_t)b*D_*L_;

    for (int sub = 0; sub < 4; sub++){
        int l0 = blockIdx.y*128 + sub*32;
        __syncthreads();  // weights ready (sub=0); xt/cbuf reuse safe (sub>0)

        for (int i = tid; i < D_*32; i += 128){
            int d = i>>5, l = i&31;
            int ll = l0 + l;
            int pos;
            if (k==0) pos = ll;
            else if (k==2) pos = L_-1-ll;
            else {
                int lv = (k==1) ? ll : (L_-1-ll);
                int w = lv / H_, h = lv - w*H_;
                pos = h*W_ + w;
            }
            xt[d*36 + l] = xb[(size_t)d*L_ + pos];
        }
        __syncthreads();

        // register-tiled 38x32 = (c) x (l) GEMM over d=96
        int ci = tid & 15, lj = tid >> 4;
        float a0[4]={0,0,0,0}, a1[4]={0,0,0,0}, a2[4]={0,0,0,0};
        #pragma unroll 4
        for (int d = 0; d < D_; d++){
            float w0 = ws[ci*97+d];
            float w1 = ws[(ci+16)*97+d];
            float w2 = (ci<6) ? ws[(ci+32)*97+d] : 0.f;
            float4 xv = *(const float4*)&xt[d*36 + lj*4];
            a0[0]=fmaf(w0,xv.x,a0[0]); a0[1]=fmaf(w0,xv.y,a0[1]);
            a0[2]=fmaf(w0,xv.z,a0[2]); a0[3]=fmaf(w0,xv.w,a0[3]);
            a1[0]=fmaf(w1,xv.x,a1[0]); a1[1]=fmaf(w1,xv.y,a1[1]);
            a1[2]=fmaf(w1,xv.z,a1[2]); a1[3]=fmaf(w1,xv.w,a1[3]);
            a2[0]=fmaf(w2,xv.x,a2[0]); a2[1]=fmaf(w2,xv.y,a2[1]);
            a2[2]=fmaf(w2,xv.z,a2[2]); a2[3]=fmaf(w2,xv.w,a2[3]);
        }
        #pragma unroll
        for (int j=0;j<4;j++){
            int l = lj*4+j;
            cbuf[ci*33 + l] = a0[j];
            cbuf[(ci+16)*33 + l] = a1[j];
            if (ci<6) cbuf[(ci+32)*33 + l] = a2[j];
        }
        __syncthreads();

        // epilogue: delta / delta*u over all (d,l), all 128 threads
        #pragma unroll 4
        for (int it = 0; it < 24; it++){
            int i = it*128 + tid;
            int l = i/96, d = i - l*96;
            float s = sbias[d];
            #pragma unroll
            for (int r=0;r<R_;r++) s = fmaf(cbuf[r*33+l], wdT[r*D_+d], s);
            float dlt = (s > 15.f) ? s : __logf(1.f + __expf(s));
            float u = xt[d*36+l];
            float2 v; v.x = dlt; v.y = dlt*u;
            *(float2*)&g_dd[(((size_t)bk*L_ + (l0+l))*D_ + d)*2] = v;
        }
        // epilogue: (B,C) interleave
        #pragma unroll
        for (int it = 0; it < 4; it++){
            int i = it*128 + tid;
            int l = i>>4, n = i&15;
            float2 v;
            v.x = cbuf[(R_+n)*33 + l];
            v.y = cbuf[(R_+N_+n)*33 + l];
            *(float2*)&g_bc[(((size_t)bk*L_ + (l0+l))*N_ + n)*2] = v;
        }
    }
}

// ---------------------------------------------------------------------------
// Kernel 2: selective scan. 96 blocks x 128 thr; block = (bk, 8 d-chains).
// Warp = 2 chains, lane = state n. 8-deep register prefetch pipeline;
// two shfl_xor levels in-loop -> 4 partials/chain; conflict-free reduce.
// ---------------------------------------------------------------------------
#define CH 64
#define PF 8
#define PROW 36
__global__ __launch_bounds__(128) void scan_kernel(const float* __restrict__ A_logs)
{
    __shared__ __align__(16) float s_dd[2][CH*16];  // [l][8 chains][2]
    __shared__ __align__(16) float s_bc[2][CH*32];  // [l][16 n][2]
    __shared__ __align__(16) float s_p [CH*PROW];   // [l][8 chains][4 partials]

    int bk = blockIdx.x / 12; int dblk = blockIdx.x % 12; int d0 = dblk*8;
    int k = bk & 3;
    int tid = threadIdx.x;
    int wid = tid>>5, lane = tid&31;
    int g = lane>>4, n = lane&15;
    int cidx = wid*2+g;
    int d = d0 + cidx;
    float Ah = -expf(A_logs[(k*D_+d)*N_ + n]) * 1.4426950408889634f;
    float h = 0.f;

    const float* gdd = g_dd + (size_t)bk*L_*D_*2;
    const float* gbc = g_bc + (size_t)bk*L_*N_*2;
    float* gy = g_y + (size_t)bk*L_*D_;

    // prefetch chunk 0
    {
        for (int i = tid; i < CH*4; i += 128){
            int l = i>>2, q = i&3;
            cp16(&s_dd[0][l*16 + q*4], gdd + ((size_t)l*D_ + d0)*2 + q*4);
        }
        for (int i = tid; i < CH*8; i += 128){
            int l = i>>3, q = i&7;
            cp16(&s_bc[0][l*32 + q*4], gbc + (size_t)l*N_*2 + q*4);
        }
        cp_commit();
    }

    const int NCH = L_/CH;
    for (int c = 0; c < NCH; c++){
        int buf = c & 1;
        if (c+1 < NCH){
            int lb = (c+1)*CH;
            for (int i = tid; i < CH*4; i += 128){
                int l = i>>2, q = i&3;
                cp16(&s_dd[buf^1][l*16 + q*4], gdd + ((size_t)(lb+l)*D_ + d0)*2 + q*4);
            }
            for (int i = tid; i < CH*8; i += 128){
                int l = i>>3, q = i&7;
                cp16(&s_bc[buf^1][l*32 + q*4], gbc + (size_t)(lb+l)*N_*2 + q*4);
            }
            cp_commit();
            cp_wait<1>();
        } else {
            cp_wait<0>();
        }
        __syncthreads();   // S1: chunk data ready; prev reduce's s_p reads done

        const float* pdd = &s_dd[buf][cidx*2];
        const float* pbc = &s_bc[buf][n*2];
        float2 rdd[PF], rbc[PF]; float ra[PF];
        #pragma unroll
        for (int j = 0; j < PF; j++){
            rdd[j] = *(const float2*)(pdd + j*16);
            rbc[j] = *(const float2*)(pbc + j*32);
            ra[j]  = ex2f(rdd[j].x * Ah);
        }
        #pragma unroll
        for (int t = 0; t < CH; t++){
            int j = t & (PF-1);
            h = fmaf(ra[j], h, rdd[j].y * rbc[j].x);
            float p = h * rbc[j].y;
            p += __shfl_xor_sync(0xffffffffu, p, 8);
            p += __shfl_xor_sync(0xffffffffu, p, 4);
            if (n < 4) s_p[t*PROW + cidx*4 + n] = p;
            if (t + PF < CH){
                rdd[j] = *(const float2*)(pdd + (t+PF)*16);
                rbc[j] = *(const float2*)(pbc + (t+PF)*32);
                ra[j]  = ex2f(rdd[j].x * Ah);
            }
        }
        __syncthreads();   // S2: s_p complete; s_dd/s_bc[buf] reads done

        // reduce 4 partials per (l, chain) and store y
        int lbase = c*CH;
        #pragma unroll
        for (int it = 0; it < (CH*8)/128; it++){
            int j = it*128 + tid;
            int l = j>>3, c8 = j&7;
            float4 v = *(const float4*)&s_p[l*PROW + c8*4];
            gy[(size_t)(lbase+l)*D_ + d0 + c8] = (v.x+v.y)+(v.z+v.w);
        }
        // no barrier here: next iteration's S1 orders s_p reuse; cp.async
        // issued below S2 only touches the buffer whose readers finished.
    }
}

// ---------------------------------------------------------------------------
// Kernel 3: cross-merge + Ds*x + LayerNorm(D). x staged via smem (coalesced).
// ---------------------------------------------------------------------------
__global__ __launch_bounds__(128) void merge_kernel(
    const float* __restrict__ x, const float* __restrict__ Ds,
    const float* __restrict__ nw, const float* __restrict__ nb,
    float* __restrict__ out)
{
    __shared__ float xt[D_*33];
    int tid = threadIdx.x;
    int pix0 = blockIdx.x*32;
    int b = pix0 / L_;
    int rem0 = pix0 - b*L_;

    const float* xb = x + (size_t)b*D_*L_;
    for (int i = tid; i < D_*32; i += 128){
        int dd = i>>5, p = i&31;
        xt[dd*33 + p] = xb[(size_t)dd*L_ + rem0 + p];
    }
    __syncthreads();

    int wid = tid>>5, lane = tid&31;
    for (int pp = wid; pp < 32; pp += 4){
        int rem = rem0 + pp;
        int hh = rem / W_;
        int ww = rem - hh*W_;
        int l_wh = ww*H_ + hh;

        const float* y0 = g_y + ((size_t)(b*4+0)*L_ + rem)*D_;
        const float* y1 = g_y + ((size_t)(b*4+1)*L_ + l_wh)*D_;
        const float* y2 = g_y + ((size_t)(b*4+2)*L_ + (L_-1-rem))*D_;
        const float* y3 = g_y + ((size_t)(b*4+3)*L_ + (L_-1-l_wh))*D_;

        float v[3]; float s = 0.f, ss = 0.f;
        #pragma unroll
        for (int j=0;j<3;j++){
            int dd = lane + 32*j;
            float dsum = Ds[dd] + Ds[D_+dd] + Ds[2*D_+dd] + Ds[3*D_+dd];
            float acc = y0[dd] + y1[dd] + y2[dd] + y3[dd] + xt[dd*33+pp] * dsum;
            v[j] = acc; s += acc; ss = fmaf(acc, acc, ss);
        }
        #pragma unroll
        for (int o=16;o>0;o>>=1){
            s  += __shfl_xor_sync(0xffffffffu, s,  o);
            ss += __shfl_xor_sync(0xffffffffu, ss, o);
        }
        float mu  = s * (1.f/D_);
        float var = ss * (1.f/D_) - mu*mu;
        float rstd = rsqrtf(var + 1e-5f);
        float* op = out + ((size_t)b*L_ + rem)*D_;
        #pragma unroll
        for (int j=0;j<3;j++){
            int dd = lane + 32*j;
            op[dd] = (v[j]-mu)*rstd*nw[dd] + nb[dd];
        }
    }
}

// ---------------------------------------------------------------------------
extern "C" void kernel_launch(void* const* d_in, const int* in_sizes, int n_in,
                              void* d_out, int out_size)
{
    const float* x      = (const float*)d_in[0];
    const float* xpw    = (const float*)d_in[1];
    const float* dtw    = (const float*)d_in[2];
    const float* dtb    = (const float*)d_in[3];
    const float* A_logs = (const float*)d_in[4];
    const float* Ds     = (const float*)d_in[5];
    const float* nw     = (const float*)d_in[6];
    const float* nb     = (const float*)d_in[7];
    float* out = (float*)d_out;

    proj_kernel<<<dim3(B_*K_, L_/128), 128>>>(x, xpw, dtw, dtb);
    scan_kernel<<<B_*K_*12, 128>>>(A_logs);
    merge_kernel<<<B_*L_/32, 128>>>(x, Ds, nw, nb, out);
}

// round 7
// speedup vs baseline: 3.5134x; 1.0681x over previous
#include <cuda_runtime.h>
#include <cstdint>

#define B_ 2
#define D_ 96
#define H_ 96
#define W_ 96
#define L_ (H_*W_)        // 9216
#define K_ 4
#define N_ 16
#define R_ 6
#define CDIM (R_ + 2*N_)  // 38

// Scratch (allocation-free: __device__ globals)
__device__ float g_dd[B_*K_*L_*D_*2];   // (bk, l, d, {delta, delta*u})
__device__ float g_bc[B_*K_*L_*N_*2];   // (bk, l, n, {B, C})
__device__ float g_y [B_*K_*L_*D_];     // (bk, l, d)

__device__ __forceinline__ float ex2f(float x){
    float y; asm("ex2.approx.ftz.f32 %0, %1;" : "=f"(y) : "f"(x)); return y;
}
__device__ __forceinline__ void cp16(void* dst_smem, const void* src){
    unsigned s = (unsigned)__cvta_generic_to_shared(dst_smem);
    asm volatile("cp.async.ca.shared.global [%0], [%1], 16;\n" :: "r"(s), "l"(src));
}
__device__ __forceinline__ void cp_commit(){ asm volatile("cp.async.commit_group;\n"); }
template<int n> __device__ __forceinline__ void cp_wait(){
    asm volatile("cp.async.wait_group %0;\n" :: "n"(n));
}

// ---------------------------------------------------------------------------
// Kernel 1: projection. 256 threads = two concurrent 32-l halves sharing one
// smem weight copy. Dynamic smem (~55KB). All float4-read regions padded to
// 16B-aligned float offsets (WS_F padded to 3688: 3688+576+96 = 4360 ≡ 0 mod 4).
// ---------------------------------------------------------------------------
#define WS_F   (CDIM*97 + 2)    // 3688 (padded for alignment)
#define XT_F   (D_*36)          // 3456 per-half (≡0 mod 4)
#define CB_F   (CDIM*33)        // per-half (scalar access only)
__global__ __launch_bounds__(256) void proj_kernel(
    const float* __restrict__ x, const float* __restrict__ xpw,
    const float* __restrict__ dtw, const float* __restrict__ dtb)
{
    extern __shared__ float sm[];
    float* ws   = sm;                       // [CDIM][97] (+2 pad)
    float* wdT  = ws + WS_F;                // [R][D]
    float* sbias= wdT + R_*D_;              // [D]
    float* xt0  = sbias + D_;               // 2 x [D][36]  (16B-aligned)
    float* cb0  = xt0 + 2*XT_F;             // 2 x [CDIM][33]

    int bk = blockIdx.x; int b = bk>>2; int k = bk&3;
    int tid = threadIdx.x;
    int half = tid>>7, htid = tid&127;
    float* xt = xt0 + half*XT_F;
    float* cbuf = cb0 + half*CB_F;
    int l0 = blockIdx.y*64 + half*32;

    for (int i = tid; i < CDIM*D_; i += 256){
        int c = i/D_, d = i - c*D_;
        ws[c*97+d] = xpw[k*CDIM*D_ + i];
    }
    for (int i = tid; i < D_*R_; i += 256){
        int d = i/R_, r = i - d*R_;
        wdT[r*D_+d] = dtw[k*D_*R_ + i];
    }
    if (tid < D_) sbias[tid] = dtb[k*D_+tid];

    const float* xb = x + (size_t)b*D_*L_;
    for (int i = htid; i < D_*32; i += 128){
        int d = i>>5, l = i&31;
        int ll = l0 + l;
        int pos;
        if (k==0) pos = ll;
        else if (k==2) pos = L_-1-ll;
        else {
            int lv = (k==1) ? ll : (L_-1-ll);
            int w = lv / H_, h = lv - w*H_;
            pos = h*W_ + w;
        }
        xt[d*36 + l] = xb[(size_t)d*L_ + pos];
    }
    __syncthreads();

    // register-tiled 38x32 = (c) x (l) GEMM over d=96 (per half)
    int ci = htid & 15, lj = htid >> 4;
    {
        float a0[4]={0,0,0,0}, a1[4]={0,0,0,0}, a2[4]={0,0,0,0};
        #pragma unroll 4
        for (int d = 0; d < D_; d++){
            float w0 = ws[ci*97+d];
            float w1 = ws[(ci+16)*97+d];
            float w2 = (ci<6) ? ws[(ci+32)*97+d] : 0.f;
            float4 xv = *(const float4*)&xt[d*36 + lj*4];
            a0[0]=fmaf(w0,xv.x,a0[0]); a0[1]=fmaf(w0,xv.y,a0[1]);
            a0[2]=fmaf(w0,xv.z,a0[2]); a0[3]=fmaf(w0,xv.w,a0[3]);
            a1[0]=fmaf(w1,xv.x,a1[0]); a1[1]=fmaf(w1,xv.y,a1[1]);
            a1[2]=fmaf(w1,xv.z,a1[2]); a1[3]=fmaf(w1,xv.w,a1[3]);
            a2[0]=fmaf(w2,xv.x,a2[0]); a2[1]=fmaf(w2,xv.y,a2[1]);
            a2[2]=fmaf(w2,xv.z,a2[2]); a2[3]=fmaf(w2,xv.w,a2[3]);
        }
        #pragma unroll
        for (int j=0;j<4;j++){
            int l = lj*4+j;
            cbuf[ci*33 + l] = a0[j];
            cbuf[(ci+16)*33 + l] = a1[j];
            if (ci<6) cbuf[(ci+32)*33 + l] = a2[j];
        }
    }
    __syncthreads();

    // epilogue: delta / delta*u over (d,l) of this half
    #pragma unroll 4
    for (int it = 0; it < 24; it++){
        int i = it*128 + htid;
        int l = i/96, d = i - l*96;
        float s = sbias[d];
        #pragma unroll
        for (int r=0;r<R_;r++) s = fmaf(cbuf[r*33+l], wdT[r*D_+d], s);
        float dlt = (s > 15.f) ? s : __logf(1.f + __expf(s));
        float u = xt[d*36+l];
        float2 v; v.x = dlt; v.y = dlt*u;
        *(float2*)&g_dd[(((size_t)bk*L_ + (l0+l))*D_ + d)*2] = v;
    }
    // epilogue: (B,C) interleave
    #pragma unroll
    for (int it = 0; it < 4; it++){
        int i = it*128 + htid;
        int l = i>>4, n = i&15;
        float2 v;
        v.x = cbuf[(R_+n)*33 + l];
        v.y = cbuf[(R_+N_+n)*33 + l];
        *(float2*)&g_bc[(((size_t)bk*L_ + (l0+l))*N_ + n)*2] = v;
    }
}

// ---------------------------------------------------------------------------
// Kernel 2: selective scan. 96 blocks x 128 thr; block = (bk, 8 d-chains).
// Warp = 2 chains, lane = state n. Group-of-4 software pipeline: SHFL results
// consumed one group later so their latency is hidden by prefetch/compute.
// ---------------------------------------------------------------------------
#define CH 64
#define PF 8
#define PROW 36
__global__ __launch_bounds__(128) void scan_kernel(const float* __restrict__ A_logs)
{
    __shared__ __align__(16) float s_dd[2][CH*16];  // [l][8 chains][2]
    __shared__ __align__(16) float s_bc[2][CH*32];  // [l][16 n][2]
    __shared__ __align__(16) float s_p [CH*PROW];   // [l][8 chains][4 partials]

    int bk = blockIdx.x / 12; int dblk = blockIdx.x % 12; int d0 = dblk*8;
    int k = bk & 3;
    int tid = threadIdx.x;
    int wid = tid>>5, lane = tid&31;
    int g = lane>>4, n = lane&15;
    int cidx = wid*2+g;
    int d = d0 + cidx;
    float Ah = -expf(A_logs[(k*D_+d)*N_ + n]) * 1.4426950408889634f;
    float h = 0.f;

    const float* gdd = g_dd + (size_t)bk*L_*D_*2;
    const float* gbc = g_bc + (size_t)bk*L_*N_*2;
    float* gy = g_y + (size_t)bk*L_*D_;

    // prefetch chunk 0
    {
        for (int i = tid; i < CH*4; i += 128){
            int l = i>>2, q = i&3;
            cp16(&s_dd[0][l*16 + q*4], gdd + ((size_t)l*D_ + d0)*2 + q*4);
        }
        for (int i = tid; i < CH*8; i += 128){
            int l = i>>3, q = i&7;
            cp16(&s_bc[0][l*32 + q*4], gbc + (size_t)l*N_*2 + q*4);
        }
        cp_commit();
    }

    const int NCH = L_/CH;
    for (int c = 0; c < NCH; c++){
        int buf = c & 1;
        if (c+1 < NCH){
            int lb = (c+1)*CH;
            for (int i = tid; i < CH*4; i += 128){
                int l = i>>2, q = i&3;
                cp16(&s_dd[buf^1][l*16 + q*4], gdd + ((size_t)(lb+l)*D_ + d0)*2 + q*4);
            }
            for (int i = tid; i < CH*8; i += 128){
                int l = i>>3, q = i&7;
                cp16(&s_bc[buf^1][l*32 + q*4], gbc + (size_t)(lb+l)*N_*2 + q*4);
            }
            cp_commit();
            cp_wait<1>();
        } else {
            cp_wait<0>();
        }
        __syncthreads();   // S1: chunk data ready; prev reduce's s_p reads done

        const float* pdd = &s_dd[buf][cidx*2];
        const float* pbc = &s_bc[buf][n*2];
        float ra[PF], rdu[PF], rcy[PF];
        #pragma unroll
        for (int s = 0; s < PF; s++){
            float2 dd = *(const float2*)(pdd + s*16);
            float2 bc = *(const float2*)(pbc + s*32);
            ra[s]  = ex2f(dd.x * Ah);
            rdu[s] = dd.y * bc.x;
            rcy[s] = bc.y;
        }

        float ppa[4], ps1[4];
        #pragma unroll
        for (int tg = 0; tg < CH; tg += 4){
            float cpa[4], cs1[4];
            // A: this group's recurrence + 1st-level shfl (issued, not consumed)
            #pragma unroll
            for (int j = 0; j < 4; j++){
                int s = (tg+j) & (PF-1);
                h = fmaf(ra[s], h, rdu[s]);
                cpa[j] = h * rcy[s];
                cs1[j] = __shfl_xor_sync(0xffffffffu, cpa[j], 8);
            }
            // C': previous group's 2nd level (issued, not consumed)
            float sm1[4], sh2[4];
            if (tg > 0){
                #pragma unroll
                for (int j = 0; j < 4; j++){
                    sm1[j] = ppa[j] + ps1[j];
                    sh2[j] = __shfl_xor_sync(0xffffffffu, sm1[j], 4);
                }
            }
            // B: refill prefetch slots (hides shfl latency)
            #pragma unroll
            for (int j = 0; j < 4; j++){
                int t = tg + j;
                if (t + PF < CH){
                    int s = t & (PF-1);
                    float2 dd = *(const float2*)(pdd + (t+PF)*16);
                    float2 bc = *(const float2*)(pbc + (t+PF)*32);
                    ra[s]  = ex2f(dd.x * Ah);
                    rdu[s] = dd.y * bc.x;
                    rcy[s] = bc.y;
                }
            }
            // D': previous group's final add + store
            if (tg > 0){
                #pragma unroll
                for (int j = 0; j < 4; j++){
                    float r = sm1[j] + sh2[j];
                    if (n < 4) s_p[(tg-4+j)*PROW + cidx*4 + n] = r;
                }
            }
            #pragma unroll
            for (int j = 0; j < 4; j++){ ppa[j] = cpa[j]; ps1[j] = cs1[j]; }
        }
        // flush last group
        #pragma unroll
        for (int j = 0; j < 4; j++){
            float sm1 = ppa[j] + ps1[j];
            float sh2 = __shfl_xor_sync(0xffffffffu, sm1, 4);
            float r = sm1 + sh2;
            if (n < 4) s_p[(CH-4+j)*PROW + cidx*4 + n] = r;
        }
        __syncthreads();   // S2: s_p complete; s_dd/s_bc[buf] reads done

        // reduce 4 partials per (l, chain) and store y
        int lbase = c*CH;
        #pragma unroll
        for (int it = 0; it < (CH*8)/128; it++){
            int j = it*128 + tid;
            int l = j>>3, c8 = j&7;
            float4 v = *(const float4*)&s_p[l*PROW + c8*4];
            gy[(size_t)(lbase+l)*D_ + d0 + c8] = (v.x+v.y)+(v.z+v.w);
        }
        // next iteration's S1 orders s_p reuse.
    }
}

// ---------------------------------------------------------------------------
// Kernel 3: cross-merge + Ds*x + LayerNorm(D). x staged via smem (coalesced).
// ---------------------------------------------------------------------------
__global__ __launch_bounds__(128) void merge_kernel(
    const float* __restrict__ x, const float* __restrict__ Ds,
    const float* __restrict__ nw, const float* __restrict__ nb,
    float* __restrict__ out)
{
    __shared__ float xt[D_*33];
    int tid = threadIdx.x;
    int pix0 = blockIdx.x*32;
    int b = pix0 / L_;
    int rem0 = pix0 - b*L_;

    const float* xb = x + (size_t)b*D_*L_;
    for (int i = tid; i < D_*32; i += 128){
        int dd = i>>5, p = i&31;
        xt[dd*33 + p] = xb[(size_t)dd*L_ + rem0 + p];
    }
    __syncthreads();

    int wid = tid>>5, lane = tid&31;
    for (int pp = wid; pp < 32; pp += 4){
        int rem = rem0 + pp;
        int hh = rem / W_;
        int ww = rem - hh*W_;
        int l_wh = ww*H_ + hh;

        const float* y0 = g_y + ((size_t)(b*4+0)*L_ + rem)*D_;
        const float* y1 = g_y + ((size_t)(b*4+1)*L_ + l_wh)*D_;
        const float* y2 = g_y + ((size_t)(b*4+2)*L_ + (L_-1-rem))*D_;
        const float* y3 = g_y + ((size_t)(b*4+3)*L_ + (L_-1-l_wh))*D_;

        float v[3]; float s = 0.f, ss = 0.f;
        #pragma unroll
        for (int j=0;j<3;j++){
            int dd = lane + 32*j;
            float dsum = Ds[dd] + Ds[D_+dd] + Ds[2*D_+dd] + Ds[3*D_+dd];
            float acc = y0[dd] + y1[dd] + y2[dd] + y3[dd] + xt[dd*33+pp] * dsum;
            v[j] = acc; s += acc; ss = fmaf(acc, acc, ss);
        }
        #pragma unroll
        for (int o=16;o>0;o>>=1){
            s  += __shfl_xor_sync(0xffffffffu, s,  o);
            ss += __shfl_xor_sync(0xffffffffu, ss, o);
        }
        float mu  = s * (1.f/D_);
        float var = ss * (1.f/D_) - mu*mu;
        float rstd = rsqrtf(var + 1e-5f);
        float* op = out + ((size_t)b*L_ + rem)*D_;
        #pragma unroll
        for (int j=0;j<3;j++){
            int dd = lane + 32*j;
            op[dd] = (v[j]-mu)*rstd*nw[dd] + nb[dd];
        }
    }
}

// ---------------------------------------------------------------------------
extern "C" void kernel_launch(void* const* d_in, const int* in_sizes, int n_in,
                              void* d_out, int out_size)
{
    const float* x      = (const float*)d_in[0];
    const float* xpw    = (const float*)d_in[1];
    const float* dtw    = (const float*)d_in[2];
    const float* dtb    = (const float*)d_in[3];
    const float* A_logs = (const float*)d_in[4];
    const float* Ds     = (const float*)d_in[5];
    const float* nw     = (const float*)d_in[6];
    const float* nb     = (const float*)d_in[7];
    float* out = (float*)d_out;

    const int proj_smem = (WS_F + R_*D_ + D_ + 2*XT_F + 2*CB_F) * sizeof(float);
    cudaFuncSetAttribute(proj_kernel,
                         cudaFuncAttributeMaxDynamicSharedMemorySize, proj_smem);

    proj_kernel<<<dim3(B_*K_, L_/64), 256, proj_smem>>>(x, xpw, dtw, dtb);
    scan_kernel<<<B_*K_*12, 128>>>(A_logs);
    merge_kernel<<<B_*L_/32, 128>>>(x, Ds, nw, nb, out);
}

// round 8
// speedup vs baseline: 3.6022x; 1.0253x over previous
#include <cuda_runtime.h>
#include <cstdint>

#define B_ 2
#define D_ 96
#define H_ 96
#define W_ 96
#define L_ (H_*W_)        // 9216
#define K_ 4
#define N_ 16
#define R_ 6
#define CDIM (R_ + 2*N_)  // 38

// Scratch (allocation-free: __device__ globals)
// g_dd: [bk][l/2][d][4] = {delta(e0), delta*u(e0), delta(e1), delta*u(e1)}
// g_bc: [bk][l/2][n][4] = {B(e0), C(e0), B(e1), C(e1)}
__device__ float g_dd[B_*K_*(L_/2)*D_*4];
__device__ float g_bc[B_*K_*(L_/2)*N_*4];
__device__ float g_y [B_*K_*L_*D_];     // (bk, l, d)

__device__ __forceinline__ float ex2f(float x){
    float y; asm("ex2.approx.ftz.f32 %0, %1;" : "=f"(y) : "f"(x)); return y;
}
__device__ __forceinline__ void cp16(void* dst_smem, const void* src){
    unsigned s = (unsigned)__cvta_generic_to_shared(dst_smem);
    asm volatile("cp.async.ca.shared.global [%0], [%1], 16;\n" :: "r"(s), "l"(src));
}
__device__ __forceinline__ void cp_commit(){ asm volatile("cp.async.commit_group;\n"); }
template<int n> __device__ __forceinline__ void cp_wait(){
    asm volatile("cp.async.wait_group %0;\n" :: "n"(n));
}
__device__ __forceinline__ void ffma2(unsigned long long& d, unsigned long long a,
                                      unsigned long long b, unsigned long long c){
    asm("fma.rn.f32x2 %0, %1, %2, %3;" : "=l"(d) : "l"(a), "l"(b), "l"(c));
}
__device__ __forceinline__ unsigned long long dup2(float w){
    unsigned long long r; asm("mov.b64 %0, {%1, %1};" : "=l"(r) : "f"(w)); return r;
}
__device__ __forceinline__ float2 unp2(unsigned long long v){
    float2 r; asm("mov.b64 {%0, %1}, %2;" : "=f"(r.x), "=f"(r.y) : "l"(v)); return r;
}

// ---------------------------------------------------------------------------
// Kernel 1: projection. 256 threads = two concurrent 32-l halves sharing one
// smem weight copy. GEMM inner loop uses fma.rn.f32x2 (l-pairs packed).
// ---------------------------------------------------------------------------
#define WS_F   (CDIM*97 + 2)    // 3688 (padded for 16B alignment of xt0)
#define XT_F   (D_*36)          // 3456 per-half
#define CB_F   (CDIM*33)
__global__ __launch_bounds__(256) void proj_kernel(
    const float* __restrict__ x, const float* __restrict__ xpw,
    const float* __restrict__ dtw, const float* __restrict__ dtb)
{
    extern __shared__ float sm[];
    float* ws   = sm;                       // [CDIM][97]
    float* wdT  = ws + WS_F;                // [R][D]
    float* sbias= wdT + R_*D_;              // [D]
    float* xt0  = sbias + D_;               // 2 x [D][36]  (16B-aligned)
    float* cb0  = xt0 + 2*XT_F;             // 2 x [CDIM][33]

    int bk = blockIdx.x; int b = bk>>2; int k = bk&3;
    int tid = threadIdx.x;
    int half = tid>>7, htid = tid&127;
    float* xt = xt0 + half*XT_F;
    float* cbuf = cb0 + half*CB_F;
    int l0 = blockIdx.y*64 + half*32;

    for (int i = tid; i < CDIM*D_; i += 256){
        int c = i/D_, d = i - c*D_;
        ws[c*97+d] = xpw[k*CDIM*D_ + i];
    }
    for (int i = tid; i < D_*R_; i += 256){
        int d = i/R_, r = i - d*R_;
        wdT[r*D_+d] = dtw[k*D_*R_ + i];
    }
    if (tid < D_) sbias[tid] = dtb[k*D_+tid];

    const float* xb = x + (size_t)b*D_*L_;
    for (int i = htid; i < D_*32; i += 128){
        int d = i>>5, l = i&31;
        int ll = l0 + l;
        int pos;
        if (k==0) pos = ll;
        else if (k==2) pos = L_-1-ll;
        else {
            int lv = (k==1) ? ll : (L_-1-ll);
            int w = lv / H_, h = lv - w*H_;
            pos = h*W_ + w;
        }
        xt[d*36 + l] = xb[(size_t)d*L_ + pos];
    }
    __syncthreads();

    // register-tiled 38x32 GEMM over d=96 with f32x2 (pairs over l)
    int ci = htid & 15, lj = htid >> 4;
    {
        unsigned long long A0[2]={0ull,0ull}, A1[2]={0ull,0ull}, A2[2]={0ull,0ull};
        #pragma unroll 4
        for (int d = 0; d < D_; d++){
            unsigned long long w0 = dup2(ws[ci*97+d]);
            unsigned long long w1 = dup2(ws[(ci+16)*97+d]);
            unsigned long long w2 = dup2((ci<6) ? ws[(ci+32)*97+d] : 0.f);
            ulonglong2 xp = *(const ulonglong2*)&xt[d*36 + lj*4];
            ffma2(A0[0], w0, xp.x, A0[0]); ffma2(A0[1], w0, xp.y, A0[1]);
            ffma2(A1[0], w1, xp.x, A1[0]); ffma2(A1[1], w1, xp.y, A1[1]);
            ffma2(A2[0], w2, xp.x, A2[0]); ffma2(A2[1], w2, xp.y, A2[1]);
        }
        #pragma unroll
        for (int q=0;q<2;q++){
            float2 v0 = unp2(A0[q]), v1 = unp2(A1[q]), v2 = unp2(A2[q]);
            int l = lj*4 + q*2;
            cbuf[ci*33 + l]        = v0.x;  cbuf[ci*33 + l + 1]        = v0.y;
            cbuf[(ci+16)*33 + l]   = v1.x;  cbuf[(ci+16)*33 + l + 1]   = v1.y;
            if (ci<6){
                cbuf[(ci+32)*33 + l] = v2.x; cbuf[(ci+32)*33 + l + 1] = v2.y;
            }
        }
    }
    __syncthreads();

    // epilogue: delta / delta*u -> packed 2-step layout
    #pragma unroll 4
    for (int it = 0; it < 24; it++){
        int i = it*128 + htid;
        int l = i/96, d = i - l*96;
        float s = sbias[d];
        #pragma unroll
        for (int r=0;r<R_;r++) s = fmaf(cbuf[r*33+l], wdT[r*D_+d], s);
        float dlt = (s > 15.f) ? s : __logf(1.f + __expf(s));
        float u = xt[d*36+l];
        int ll = l0 + l;
        float2 v; v.x = dlt; v.y = dlt*u;
        *(float2*)&g_dd[(((size_t)bk*(L_/2) + (ll>>1))*D_ + d)*4 + (ll&1)*2] = v;
    }
    // epilogue: (B,C) -> packed 2-step layout
    #pragma unroll
    for (int it = 0; it < 4; it++){
        int i = it*128 + htid;
        int l = i>>4, n = i&15;
        float2 v;
        v.x = cbuf[(R_+n)*33 + l];
        v.y = cbuf[(R_+N_+n)*33 + l];
        int ll = l0 + l;
        *(float2*)&g_bc[(((size_t)bk*(L_/2) + (ll>>1))*N_ + n)*4 + (ll&1)*2] = v;
    }
}

// ---------------------------------------------------------------------------
// Kernel 2: selective scan. 96 blocks x 128 thr; block = (bk, 8 d-chains).
// Warp = 2 chains, lane = state n. 2-step packed LDS.128 operands, no SHFL:
// each lane STS.64 its two partials; per-chunk bulk reduce over n.
// ---------------------------------------------------------------------------
#define CH 64
#define CH2 (CH/2)      // 32 packed rows per chunk
#define PF2 4           // prefetch depth in 2-step units
#define PROW 40         // s_p row stride (words) per (t2, chain)
// dynamic smem: s_dd 2*CH2*8*4 floats | s_bc 2*CH2*16*4 | s_p (CH2*8)*PROW
#define SDD_F (2*CH2*32)        // 2048
#define SBC_F (2*CH2*64)        // 4096
#define SP_F  (CH2*8*PROW)      // 10240
__global__ __launch_bounds__(128) void scan_kernel(const float* __restrict__ A_logs)
{
    extern __shared__ float smem[];
    float* sdd = smem;              // [2][CH2][8][4]
    float* sbc = smem + SDD_F;      // [2][CH2][16][4]
    float* sp  = smem + SDD_F + SBC_F;  // [(CH2*8)][PROW]: [n*2 + step]

    int bk = blockIdx.x / 12; int dblk = blockIdx.x % 12; int d0 = dblk*8;
    int k = bk & 3;
    int tid = threadIdx.x;
    int wid = tid>>5, lane = tid&31;
    int g = lane>>4, n = lane&15;
    int cidx = wid*2+g;
    int d = d0 + cidx;
    float Ah = -expf(A_logs[(k*D_+d)*N_ + n]) * 1.4426950408889634f;
    float h = 0.f;

    const float* gdd = g_dd + (size_t)bk*(L_/2)*D_*4;
    const float* gbc = g_bc + (size_t)bk*(L_/2)*N_*4;
    float* gy = g_y + (size_t)bk*L_*D_;

    // prefetch chunk 0
    {
        for (int i = tid; i < CH2*8; i += 128){
            int l2 = i>>3, q = i&7;
            cp16(&sdd[l2*32 + q*4], gdd + ((size_t)l2*D_ + d0)*4 + q*4);
        }
        for (int i = tid; i < CH2*16; i += 128){
            int l2 = i>>4, q = i&15;
            cp16(&sbc[l2*64 + q*4], gbc + (size_t)l2*N_*4 + q*4);
        }
        cp_commit();
    }

    float* pp = sp + cidx*PROW + n*2;   // this lane's partial slot (row stride 8*PROW per t2)

    const int NCH = L_/CH;
    for (int c = 0; c < NCH; c++){
        int buf = c & 1;
        if (c+1 < NCH){
            int lb2 = (c+1)*CH2;
            for (int i = tid; i < CH2*8; i += 128){
                int l2 = i>>3, q = i&7;
                cp16(&sdd[(buf^1)*CH2*32 + l2*32 + q*4],
                     gdd + ((size_t)(lb2+l2)*D_ + d0)*4 + q*4);
            }
            for (int i = tid; i < CH2*16; i += 128){
                int l2 = i>>4, q = i&15;
                cp16(&sbc[(buf^1)*CH2*64 + l2*64 + q*4],
                     gbc + (size_t)(lb2+l2)*N_*4 + q*4);
            }
            cp_commit();
            cp_wait<1>();
        } else {
            cp_wait<0>();
        }
        __syncthreads();   // S1: chunk ready; prev reduce's sp reads done

        const float4* pdd = (const float4*)(sdd + buf*CH2*32) + cidx;  // +8 per t2
        const float4* pbc = (const float4*)(sbc + buf*CH2*64) + n;     // +16 per t2

        float a0s[PF2], a1s[PF2], du0[PF2], du1[PF2], cy0[PF2], cy1[PF2];
        #pragma unroll
        for (int j = 0; j < PF2; j++){
            float4 dd = pdd[j*8];
            float4 bc = pbc[j*16];
            a0s[j] = ex2f(dd.x * Ah); du0[j] = dd.y * bc.x; cy0[j] = bc.y;
            a1s[j] = ex2f(dd.z * Ah); du1[j] = dd.w * bc.z; cy1[j] = bc.w;
        }
        #pragma unroll
        for (int t2 = 0; t2 < CH2; t2++){
            int j = t2 & (PF2-1);
            h = fmaf(a0s[j], h, du0[j]);
            float p0 = h * cy0[j];
            h = fmaf(a1s[j], h, du1[j]);
            float p1 = h * cy1[j];
            float2 st; st.x = p0; st.y = p1;
            *(float2*)&pp[t2*(8*PROW)] = st;
            if (t2 + PF2 < CH2){
                float4 dd = pdd[(t2+PF2)*8];
                float4 bc = pbc[(t2+PF2)*16];
                a0s[j] = ex2f(dd.x * Ah); du0[j] = dd.y * bc.x; cy0[j] = bc.y;
                a1s[j] = ex2f(dd.z * Ah); du1[j] = dd.w * bc.z; cy1[j] = bc.w;
            }
        }
        __syncthreads();   // S2: sp complete; sdd/sbc[buf] reads done

        // reduce 16 n-partials for both steps of each (t2, chain); store y
        int lbase = c*CH;
        #pragma unroll
        for (int it = 0; it < 2; it++){
            int T = it*128 + tid;          // 0..255
            int t2 = T>>3, c8 = T&7;
            const float4* q = (const float4*)&sp[(t2*8 + c8)*PROW];
            float e = 0.f, o = 0.f;
            #pragma unroll
            for (int j = 0; j < 8; j++){
                float4 v = q[j];
                e += v.x + v.z; o += v.y + v.w;
            }
            int l = lbase + t2*2;
            gy[(size_t)l*D_ + d0 + c8]     = e;
            gy[(size_t)(l+1)*D_ + d0 + c8] = o;
        }
        // next iteration's S1 orders sp reuse
    }
}

// ---------------------------------------------------------------------------
// Kernel 3: cross-merge + Ds*x + LayerNorm(D). x staged via smem (coalesced).
// ---------------------------------------------------------------------------
__global__ __launch_bounds__(128) void merge_kernel(
    const float* __restrict__ x, const float* __restrict__ Ds,
    const float* __restrict__ nw, const float* __restrict__ nb,
    float* __restrict__ out)
{
    __shared__ float xt[D_*33];
    int tid = threadIdx.x;
    int pix0 = blockIdx.x*32;
    int b = pix0 / L_;
    int rem0 = pix0 - b*L_;

    const float* xb = x + (size_t)b*D_*L_;
    for (int i = tid; i < D_*32; i += 128){
        int dd = i>>5, p = i&31;
        xt[dd*33 + p] = xb[(size_t)dd*L_ + rem0 + p];
    }
    __syncthreads();

    int wid = tid>>5, lane = tid&31;
    for (int pp = wid; pp < 32; pp += 4){
        int rem = rem0 + pp;
        int hh = rem / W_;
        int ww = rem - hh*W_;
        int l_wh = ww*H_ + hh;

        const float* y0 = g_y + ((size_t)(b*4+0)*L_ + rem)*D_;
        const float* y1 = g_y + ((size_t)(b*4+1)*L_ + l_wh)*D_;
        const float* y2 = g_y + ((size_t)(b*4+2)*L_ + (L_-1-rem))*D_;
        const float* y3 = g_y + ((size_t)(b*4+3)*L_ + (L_-1-l_wh))*D_;

        float v[3]; float s = 0.f, ss = 0.f;
        #pragma unroll
        for (int j=0;j<3;j++){
            int dd = lane + 32*j;
            float dsum = Ds[dd] + Ds[D_+dd] + Ds[2*D_+dd] + Ds[3*D_+dd];
            float acc = y0[dd] + y1[dd] + y2[dd] + y3[dd] + xt[dd*33+pp] * dsum;
            v[j] = acc; s += acc; ss = fmaf(acc, acc, ss);
        }
        #pragma unroll
        for (int o=16;o>0;o>>=1){
            s  += __shfl_xor_sync(0xffffffffu, s,  o);
            ss += __shfl_xor_sync(0xffffffffu, ss, o);
        }
        float mu  = s * (1.f/D_);
        float var = ss * (1.f/D_) - mu*mu;
        float rstd = rsqrtf(var + 1e-5f);
        float* op = out + ((size_t)b*L_ + rem)*D_;
        #pragma unroll
        for (int j=0;j<3;j++){
            int dd = lane + 32*j;
            op[dd] = (v[j]-mu)*rstd*nw[dd] + nb[dd];
        }
    }
}

// ---------------------------------------------------------------------------
extern "C" void kernel_launch(void* const* d_in, const int* in_sizes, int n_in,
                              void* d_out, int out_size)
{
    const float* x      = (const float*)d_in[0];
    const float* xpw    = (const float*)d_in[1];
    const float* dtw    = (const float*)d_in[2];
    const float* dtb    = (const float*)d_in[3];
    const float* A_logs = (const float*)d_in[4];
    const float* Ds     = (const float*)d_in[5];
    const float* nw     = (const float*)d_in[6];
    const float* nb     = (const float*)d_in[7];
    float* out = (float*)d_out;

    const int proj_smem = (WS_F + R_*D_ + D_ + 2*XT_F + 2*CB_F) * sizeof(float);
    cudaFuncSetAttribute(proj_kernel,
                         cudaFuncAttributeMaxDynamicSharedMemorySize, proj_smem);
    const int scan_smem = (SDD_F + SBC_F + SP_F) * sizeof(float);
    cudaFuncSetAttribute(scan_kernel,
                         cudaFuncAttributeMaxDynamicSharedMemorySize, scan_smem);

    proj_kernel<<<dim3(B_*K_, L_/64), 256, proj_smem>>>(x, xpw, dtw, dtb);
    scan_kernel<<<B_*K_*12, 128, scan_smem>>>(A_logs);
    merge_kernel<<<B_*L_/32, 128>>>(x, Ds, nw, nb, out);
}

// round 9
// speedup vs baseline: 4.4639x; 1.2392x over previous
#include <cuda_runtime.h>
#include <cstdint>

#define B_ 2
#define D_ 96
#define H_ 96
#define W_ 96
#define L_ (H_*W_)        // 9216
#define K_ 4
#define N_ 16
#define R_ 6
#define CDIM (R_ + 2*N_)  // 38

// Scratch (allocation-free: __device__ globals)
// g_dd: [bk][l/2][d][4] = {delta(e0), delta*u(e0), delta(e1), delta*u(e1)}
// g_bc: [bk][l/2][n][4] = {B(e0), C(e0), B(e1), C(e1)}
__device__ float g_dd[B_*K_*(L_/2)*D_*4];
__device__ float g_bc[B_*K_*(L_/2)*N_*4];
__device__ float g_y [B_*K_*L_*D_];     // (bk, l, d)
__device__ float g_xT[B_*D_*L_];        // x transposed: [b][d][w*H+h]

__device__ __forceinline__ float ex2f(float x){
    float y; asm("ex2.approx.ftz.f32 %0, %1;" : "=f"(y) : "f"(x)); return y;
}
__device__ __forceinline__ void cp16(void* dst_smem, const void* src){
    unsigned s = (unsigned)__cvta_generic_to_shared(dst_smem);
    asm volatile("cp.async.ca.shared.global [%0], [%1], 16;\n" :: "r"(s), "l"(src));
}
__device__ __forceinline__ void cp_commit(){ asm volatile("cp.async.commit_group;\n"); }
template<int n> __device__ __forceinline__ void cp_wait(){
    asm volatile("cp.async.wait_group %0;\n" :: "n"(n));
}
__device__ __forceinline__ void ffma2(unsigned long long& d, unsigned long long a,
                                      unsigned long long b, unsigned long long c){
    asm("fma.rn.f32x2 %0, %1, %2, %3;" : "=l"(d) : "l"(a), "l"(b), "l"(c));
}
__device__ __forceinline__ unsigned long long dup2(float w){
    unsigned long long r; asm("mov.b64 %0, {%1, %1};" : "=l"(r) : "f"(w)); return r;
}
__device__ __forceinline__ float2 unp2(unsigned long long v){
    float2 r; asm("mov.b64 {%0, %1}, %2;" : "=f"(r.x), "=f"(r.y) : "l"(v)); return r;
}

// ---------------------------------------------------------------------------
// Kernel 0: transpose x (h,w) per (b,d) so the wh-scan directions read
// coalesced. 32x32 tiles, block (32,8).
// ---------------------------------------------------------------------------
__global__ __launch_bounds__(256) void transpose_kernel(const float* __restrict__ x)
{
    __shared__ float t[32][33];
    int bd = blockIdx.x;               // 0..B_*D_-1
    int th = blockIdx.y / 3, tw = blockIdx.y % 3;
    int tx = threadIdx.x, ty = threadIdx.y;
    const float* src = x + (size_t)bd*L_;
    float* dst = g_xT + (size_t)bd*L_;
    int h0 = th*32, w0 = tw*32;
    #pragma unroll
    for (int i = 0; i < 4; i++)
        t[ty + i*8][tx] = src[(h0 + ty + i*8)*W_ + w0 + tx];
    __syncthreads();
    #pragma unroll
    for (int i = 0; i < 4; i++)
        dst[(w0 + ty + i*8)*H_ + h0 + tx] = t[tx][ty + i*8];
}

// ---------------------------------------------------------------------------
// Kernel 1: projection. 256 threads = two concurrent 32-l halves sharing one
// smem weight copy. 4-d-block GEMM with float4 weight loads; all x loads
// coalesced (k=1,3 read g_xT).
// ---------------------------------------------------------------------------
#define WSQ_F  (CDIM*100)       // 3800, row stride 100 floats (16B-aligned rows)
#define XT_F   (D_*36)          // 3456 per-half
#define CB_F   (CDIM*33)
__global__ __launch_bounds__(256) void proj_kernel(
    const float* __restrict__ x, const float* __restrict__ xpw,
    const float* __restrict__ dtw, const float* __restrict__ dtb)
{
    extern __shared__ float sm[];
    float* wsq  = sm;                       // [CDIM][100]
    float* wdT  = wsq + WSQ_F;              // [R][D]
    float* sbias= wdT + R_*D_;              // [D]
    float* xt0  = sbias + D_;               // 2 x [D][36]  (offset 4472 ≡ 0 mod 4)
    float* cb0  = xt0 + 2*XT_F;             // 2 x [CDIM][33]

    int bk = blockIdx.x; int b = bk>>2; int k = bk&3;
    int tid = threadIdx.x;
    int half = tid>>7, htid = tid&127;
    float* xt = xt0 + half*XT_F;
    float* cbuf = cb0 + half*CB_F;
    int l0 = blockIdx.y*64 + half*32;

    for (int i = tid; i < CDIM*D_; i += 256){
        int c = i/D_, d = i - c*D_;
        wsq[c*100+d] = xpw[k*CDIM*D_ + i];
    }
    for (int i = tid; i < D_*R_; i += 256){
        int d = i/R_, r = i - d*R_;
        wdT[r*D_+d] = dtw[k*D_*R_ + i];
    }
    if (tid < D_) sbias[tid] = dtb[k*D_+tid];

    // coalesced xs tile load: k=0,2 from x; k=1,3 from g_xT; k>=2 reversed
    const float* xsrc = ((k&1)==0) ? (x + (size_t)b*D_*L_)
                                   : (g_xT + (size_t)b*D_*L_);
    for (int i = htid; i < D_*32; i += 128){
        int d = i>>5, l = i&31;
        int ll = l0 + l;
        int pos = (k<2) ? ll : (L_-1-ll);
        xt[d*36 + l] = xsrc[(size_t)d*L_ + pos];
    }
    __syncthreads();

    // register-tiled 38x32 GEMM over d=96, 4-d blocks, float4 weights
    int ci = htid & 15, lj = htid >> 4;
    {
        unsigned long long A0[2]={0ull,0ull}, A1[2]={0ull,0ull}, A2[2]={0ull,0ull};
        #pragma unroll 3
        for (int d4 = 0; d4 < D_/4; d4++){
            float4 w0 = *(const float4*)&wsq[ci*100 + d4*4];
            float4 w1 = *(const float4*)&wsq[(ci+16)*100 + d4*4];
            float4 w2 = (ci<6) ? *(const float4*)&wsq[(ci+32)*100 + d4*4]
                               : make_float4(0.f,0.f,0.f,0.f);
            const float* wq0 = &w0.x; const float* wq1 = &w1.x; const float* wq2 = &w2.x;
            #pragma unroll
            for (int j = 0; j < 4; j++){
                ulonglong2 xp = *(const ulonglong2*)&xt[(d4*4+j)*36 + lj*4];
                unsigned long long b0 = dup2(wq0[j]);
                unsigned long long b1 = dup2(wq1[j]);
                unsigned long long b2 = dup2(wq2[j]);
                ffma2(A0[0], b0, xp.x, A0[0]); ffma2(A0[1], b0, xp.y, A0[1]);
                ffma2(A1[0], b1, xp.x, A1[0]); ffma2(A1[1], b1, xp.y, A1[1]);
                ffma2(A2[0], b2, xp.x, A2[0]); ffma2(A2[1], b2, xp.y, A2[1]);
            }
        }
        #pragma unroll
        for (int q=0;q<2;q++){
            float2 v0 = unp2(A0[q]), v1 = unp2(A1[q]), v2 = unp2(A2[q]);
            int l = lj*4 + q*2;
            cbuf[ci*33 + l]        = v0.x;  cbuf[ci*33 + l + 1]        = v0.y;
            cbuf[(ci+16)*33 + l]   = v1.x;  cbuf[(ci+16)*33 + l + 1]   = v1.y;
            if (ci<6){
                cbuf[(ci+32)*33 + l] = v2.x; cbuf[(ci+32)*33 + l + 1] = v2.y;
            }
        }
    }
    __syncthreads();

    // epilogue: delta / delta*u -> packed 2-step layout
    #pragma unroll 4
    for (int it = 0; it < 24; it++){
        int i = it*128 + htid;
        int l = i/96, d = i - l*96;
        float s = sbias[d];
        #pragma unroll
        for (int r=0;r<R_;r++) s = fmaf(cbuf[r*33+l], wdT[r*D_+d], s);
        float dlt = (s > 15.f) ? s : __logf(1.f + __expf(s));
        float u = xt[d*36+l];
        int ll = l0 + l;
        float2 v; v.x = dlt; v.y = dlt*u;
        *(float2*)&g_dd[(((size_t)bk*(L_/2) + (ll>>1))*D_ + d)*4 + (ll&1)*2] = v;
    }
    // epilogue: (B,C) -> packed 2-step layout
    #pragma unroll
    for (int it = 0; it < 4; it++){
        int i = it*128 + htid;
        int l = i>>4, n = i&15;
        float2 v;
        v.x = cbuf[(R_+n)*33 + l];
        v.y = cbuf[(R_+N_+n)*33 + l];
        int ll = l0 + l;
        *(float2*)&g_bc[(((size_t)bk*(L_/2) + (ll>>1))*N_ + n)*4 + (ll&1)*2] = v;
    }
}

// ---------------------------------------------------------------------------
// Kernel 2: selective scan. 96 blocks x 128 thr; block = (bk, 8 d-chains).
// Warp = 2 chains, lane = state n. 3-stage pipeline: load (t2 for t2+6) ->
// cook (t2 for t2+4, distance 2 after its load covers LDS latency) ->
// consume (t2). No same-iteration LDS->use dependence anywhere.
// ---------------------------------------------------------------------------
#define CH 64
#define CH2 (CH/2)      // 32 packed rows per chunk
#define PROW 36         // partial row stride (floats): 144B -> min-wavefront reduce
#define SDD_F (2*CH2*32)        // 2048
#define SBC_F (2*CH2*64)        // 4096
#define SP_F  (CH2*8*PROW)      // 9216
__global__ __launch_bounds__(128) void scan_kernel(const float* __restrict__ A_logs)
{
    extern __shared__ float smem[];
    float* sdd = smem;                  // [2][CH2][8][4]
    float* sbc = smem + SDD_F;          // [2][CH2][16][4]
    float* sp  = smem + SDD_F + SBC_F;  // [(CH2*8)][PROW]

    int bk = blockIdx.x / 12; int dblk = blockIdx.x % 12; int d0 = dblk*8;
    int k = bk & 3;
    int tid = threadIdx.x;
    int wid = tid>>5, lane = tid&31;
    int g = lane>>4, n = lane&15;
    int cidx = wid*2+g;
    int d = d0 + cidx;
    float Ah = -expf(A_logs[(k*D_+d)*N_ + n]) * 1.4426950408889634f;
    float h = 0.f;

    const float* gdd = g_dd + (size_t)bk*(L_/2)*D_*4;
    const float* gbc = g_bc + (size_t)bk*(L_/2)*N_*4;
    float* gy = g_y + (size_t)bk*L_*D_;

    // prefetch chunk 0
    {
        for (int i = tid; i < CH2*8; i += 128){
            int l2 = i>>3, q = i&7;
            cp16(&sdd[l2*32 + q*4], gdd + ((size_t)l2*D_ + d0)*4 + q*4);
        }
        for (int i = tid; i < CH2*16; i += 128){
            int l2 = i>>4, q = i&15;
            cp16(&sbc[l2*64 + q*4], gbc + (size_t)l2*N_*4 + q*4);
        }
        cp_commit();
    }

    float* pp = sp + cidx*PROW + n*2;   // this lane's partial slot

    const int NCH = L_/CH;
    for (int c = 0; c < NCH; c++){
        int buf = c & 1;
        if (c+1 < NCH){
            int lb2 = (c+1)*CH2;
            for (int i = tid; i < CH2*8; i += 128){
                int l2 = i>>3, q = i&7;
                cp16(&sdd[(buf^1)*CH2*32 + l2*32 + q*4],
                     gdd + ((size_t)(lb2+l2)*D_ + d0)*4 + q*4);
            }
            for (int i = tid; i < CH2*16; i += 128){
                int l2 = i>>4, q = i&15;
                cp16(&sbc[(buf^1)*CH2*64 + l2*64 + q*4],
                     gbc + (size_t)(lb2+l2)*N_*4 + q*4);
            }
            cp_commit();
            cp_wait<1>();
        } else {
            cp_wait<0>();
        }
        __syncthreads();   // S1: chunk ready; prev reduce's sp reads done

        const float4* pdd = (const float4*)(sdd + buf*CH2*32) + cidx;  // +8 per t2
        const float4* pbc = (const float4*)(sbc + buf*CH2*64) + n;     // +16 per t2

        float4 rawd[2], rawb[2];
        float a0c[4], a1c[4], du0c[4], du1c[4], cy0c[4], cy1c[4];
        // prologue: cook slots 0..3 directly; preload raw for t2=4,5
        #pragma unroll
        for (int j = 0; j < 4; j++){
            float4 dd = pdd[j*8];
            float4 bc = pbc[j*16];
            a0c[j]=ex2f(dd.x*Ah); du0c[j]=dd.y*bc.x; cy0c[j]=bc.y;
            a1c[j]=ex2f(dd.z*Ah); du1c[j]=dd.w*bc.z; cy1c[j]=bc.w;
        }
        rawd[0] = pdd[4*8];  rawb[0] = pbc[4*16];
        rawd[1] = pdd[5*8];  rawb[1] = pbc[5*16];

        #pragma unroll
        for (int t2 = 0; t2 < CH2; t2++){
            int j = t2 & 3, jr = t2 & 1;
            // consume
            h = fmaf(a0c[j], h, du0c[j]);
            float p0 = h * cy0c[j];
            h = fmaf(a1c[j], h, du1c[j]);
            float p1 = h * cy1c[j];
            float2 st; st.x = p0; st.y = p1;
            *(float2*)&pp[t2*(8*PROW)] = st;
            // cook for t2+4 (raw loaded at t2-2)
            if (t2 < CH2-4){
                float4 dd = rawd[jr], bc = rawb[jr];
                a0c[j]=ex2f(dd.x*Ah); du0c[j]=dd.y*bc.x; cy0c[j]=bc.y;
                a1c[j]=ex2f(dd.z*Ah); du1c[j]=dd.w*bc.z; cy1c[j]=bc.w;
            }
            // load raw for t2+6
            if (t2 < CH2-6){
                rawd[jr] = pdd[(t2+6)*8];
                rawb[jr] = pbc[(t2+6)*16];
            }
        }
        __syncthreads();   // S2: sp complete; sdd/sbc[buf] reads done

        // reduce 16 n-partials for both steps of each (t2, chain); store y
        int lbase = c*CH;
        #pragma unroll
        for (int it = 0; it < 2; it++){
            int T = it*128 + tid;
            int t2 = T>>3, c8 = T&7;
            const float4* q = (const float4*)&sp[(t2*8 + c8)*PROW];
            float e = 0.f, o = 0.f;
            #pragma unroll
            for (int j = 0; j < 8; j++){
                float4 v = q[j];
                e += v.x + v.z; o += v.y + v.w;
            }
            int l = lbase + t2*2;
            gy[(size_t)l*D_ + d0 + c8]     = e;
            gy[(size_t)(l+1)*D_ + d0 + c8] = o;
        }
        // next iteration's S1 orders sp reuse
    }
}

// ---------------------------------------------------------------------------
// Kernel 3: cross-merge + Ds*x + LayerNorm(D). x staged via smem (coalesced).
// ---------------------------------------------------------------------------
__global__ __launch_bounds__(128) void merge_kernel(
    const float* __restrict__ x, const float* __restrict__ Ds,
    const float* __restrict__ nw, const float* __restrict__ nb,
    float* __restrict__ out)
{
    __shared__ float xt[D_*33];
    int tid = threadIdx.x;
    int pix0 = blockIdx.x*32;
    int b = pix0 / L_;
    int rem0 = pix0 - b*L_;

    const float* xb = x + (size_t)b*D_*L_;
    for (int i = tid; i < D_*32; i += 128){
        int dd = i>>5, p = i&31;
        xt[dd*33 + p] = xb[(size_t)dd*L_ + rem0 + p];
    }
    __syncthreads();

    int wid = tid>>5, lane = tid&31;
    for (int pp = wid; pp < 32; pp += 4){
        int rem = rem0 + pp;
        int hh = rem / W_;
        int ww = rem - hh*W_;
        int l_wh = ww*H_ + hh;

        const float* y0 = g_y + ((size_t)(b*4+0)*L_ + rem)*D_;
        const float* y1 = g_y + ((size_t)(b*4+1)*L_ + l_wh)*D_;
        const float* y2 = g_y + ((size_t)(b*4+2)*L_ + (L_-1-rem))*D_;
        const float* y3 = g_y + ((size_t)(b*4+3)*L_ + (L_-1-l_wh))*D_;

        float v[3]; float s = 0.f, ss = 0.f;
        #pragma unroll
        for (int j=0;j<3;j++){
            int dd = lane + 32*j;
            float dsum = Ds[dd] + Ds[D_+dd] + Ds[2*D_+dd] + Ds[3*D_+dd];
            float acc = y0[dd] + y1[dd] + y2[dd] + y3[dd] + xt[dd*33+pp] * dsum;
            v[j] = acc; s += acc; ss = fmaf(acc, acc, ss);
        }
        #pragma unroll
        for (int o=16;o>0;o>>=1){
            s  += __shfl_xor_sync(0xffffffffu, s,  o);
            ss += __shfl_xor_sync(0xffffffffu, ss, o);
        }
        float mu  = s * (1.f/D_);
        float var = ss * (1.f/D_) - mu*mu;
        float rstd = rsqrtf(var + 1e-5f);
        float* op = out + ((size_t)b*L_ + rem)*D_;
        #pragma unroll
        for (int j=0;j<3;j++){
            int dd = lane + 32*j;
            op[dd] = (v[j]-mu)*rstd*nw[dd] + nb[dd];
        }
    }
}

// ---------------------------------------------------------------------------
extern "C" void kernel_launch(void* const* d_in, const int* in_sizes, int n_in,
                              void* d_out, int out_size)
{
    const float* x      = (const float*)d_in[0];
    const float* xpw    = (const float*)d_in[1];
    const float* dtw    = (const float*)d_in[2];
    const float* dtb    = (const float*)d_in[3];
    const float* A_logs = (const float*)d_in[4];
    const float* Ds     = (const float*)d_in[5];
    const float* nw     = (const float*)d_in[6];
    const float* nb     = (const float*)d_in[7];
    float* out = (float*)d_out;

    const int proj_smem = (WSQ_F + R_*D_ + D_ + 2*XT_F + 2*CB_F) * sizeof(float);
    cudaFuncSetAttribute(proj_kernel,
                         cudaFuncAttributeMaxDynamicSharedMemorySize, proj_smem);
    const int scan_smem = (SDD_F + SBC_F + SP_F) * sizeof(float);
    cudaFuncSetAttribute(scan_kernel,
                         cudaFuncAttributeMaxDynamicSharedMemorySize, scan_smem);

    transpose_kernel<<<dim3(B_*D_, 9), dim3(32,8)>>>(x);
    proj_kernel<<<dim3(B_*K_, L_/64), 256, proj_smem>>>(x, xpw, dtw, dtb);
    scan_kernel<<<B_*K_*12, 128, scan_smem>>>(A_logs);
    merge_kernel<<<B_*L_/32, 128>>>(x, Ds, nw, nb, out);
}